// round 1
// baseline (speedup 1.0000x reference)
#include <cuda_runtime.h>
#include <math.h>

#define LSEQ 2048
#define DM   1024
#define DI   2048
#define DS   16
#define DTR  64
#define DBLC 96   /* DTR + 2*DS */

// ---------------- scratch (static device buffers; no allocation) ------------
__device__ float g_x  [LSEQ * DM];      // residual stream
__device__ float g_h  [LSEQ * DM];      // post-layernorm
__device__ float g_xz [LSEQ * 2 * DI];  // in_proj out: [xc | z]
__device__ float g_xc [LSEQ * DI];      // conv+silu out
__device__ float g_dbl[LSEQ * DBLC];    // x_proj out: [dt_lr | B | C]
__device__ float g_dt [LSEQ * DI];      // dt after proj+softplus
__device__ float g_y  [LSEQ * DI];      // scan out (gated)

// ---------------- helpers ---------------------------------------------------
__device__ __forceinline__ float siluf(float x) {
    return x / (1.0f + __expf(-x));
}
__device__ __forceinline__ float softplusf(float x) {
    if (x > 20.0f) return x;
    return log1pf(__expf(x));
}

// ---------------- copy ------------------------------------------------------
__global__ void copy_kernel(const float* __restrict__ src, float* __restrict__ dst, int n) {
    int i = blockIdx.x * blockDim.x + threadIdx.x;
    if (i < n) dst[i] = src[i];
}

// ---------------- layernorm (one block per row of 1024) ---------------------
__global__ void __launch_bounds__(256) ln_kernel(
    const float* __restrict__ x, const float* __restrict__ w,
    const float* __restrict__ b, float* __restrict__ out)
{
    int row = blockIdx.x;
    int t   = threadIdx.x;
    const float* xr = x + row * DM;

    float4 v = *(const float4*)(xr + t * 4);
    float s  = v.x + v.y + v.z + v.w;
    float ss = v.x * v.x + v.y * v.y + v.z * v.z + v.w * v.w;

    #pragma unroll
    for (int o = 16; o; o >>= 1) {
        s  += __shfl_xor_sync(0xffffffffu, s,  o);
        ss += __shfl_xor_sync(0xffffffffu, ss, o);
    }
    __shared__ float sred[8], ssred[8];
    __shared__ float smu, srstd;
    int wid = t >> 5, lane = t & 31;
    if (lane == 0) { sred[wid] = s; ssred[wid] = ss; }
    __syncthreads();
    if (t == 0) {
        float S = 0.f, SS = 0.f;
        #pragma unroll
        for (int i = 0; i < 8; i++) { S += sred[i]; SS += ssred[i]; }
        float mu  = S * (1.0f / DM);
        float var = SS * (1.0f / DM) - mu * mu;
        smu = mu; srstd = rsqrtf(var + 1e-5f);
    }
    __syncthreads();
    float mu = smu, rs = srstd;

    float4 wv = *(const float4*)(w + t * 4);
    float4 bv = *(const float4*)(b + t * 4);
    float4 o4;
    o4.x = (v.x - mu) * rs * wv.x + bv.x;
    o4.y = (v.y - mu) * rs * wv.y + bv.y;
    o4.z = (v.z - mu) * rs * wv.z + bv.z;
    o4.w = (v.w - mu) * rs * wv.w + bv.w;
    *(float4*)(out + row * DM + t * 4) = o4;
}

// ---------------- GEMM: C[m,n] = sum_k A[m,k] * B[n,k] (both K-major) -------
// BM=BN=128, BK=16, 8x8 per-thread, 256 threads.
// EPI 0: store; EPI 1: softplus(acc + bias[n]); EPI 2: acc + res[m*ldc+n]
template<int EPI>
__global__ void __launch_bounds__(256) gemm_nt(
    const float* __restrict__ A, int lda,
    const float* __restrict__ B, int ldb,
    float* __restrict__ C, int ldc,
    int N, int K,
    const float* __restrict__ bias,
    const float* __restrict__ res)
{
    const int BM = 128, BN = 128, BK = 16;
    __shared__ float As[BK][BM];
    __shared__ float Bs[BK][BN];

    int m0  = blockIdx.y * BM;
    int n0  = blockIdx.x * BN;
    int tid = threadIdx.x;
    int tx  = tid & 15;   // n direction
    int ty  = tid >> 4;   // m direction

    float acc[8][8];
    #pragma unroll
    for (int i = 0; i < 8; i++)
        #pragma unroll
        for (int j = 0; j < 8; j++) acc[i][j] = 0.f;

    for (int k0 = 0; k0 < K; k0 += BK) {
        // load A & B tiles (each thread: 2 float4 from each)
        #pragma unroll
        for (int it = 0; it < 2; it++) {
            int id = tid + it * 256;        // 0..511
            int r  = id >> 2;               // 0..127
            int kq = (id & 3) << 2;         // 0,4,8,12
            float4 va = *(const float4*)(A + (size_t)(m0 + r) * lda + k0 + kq);
            As[kq + 0][r] = va.x; As[kq + 1][r] = va.y;
            As[kq + 2][r] = va.z; As[kq + 3][r] = va.w;
            float4 vb;
            if (n0 + r < N) vb = *(const float4*)(B + (size_t)(n0 + r) * ldb + k0 + kq);
            else            vb = make_float4(0.f, 0.f, 0.f, 0.f);
            Bs[kq + 0][r] = vb.x; Bs[kq + 1][r] = vb.y;
            Bs[kq + 2][r] = vb.z; Bs[kq + 3][r] = vb.w;
        }
        __syncthreads();

        #pragma unroll
        for (int kk = 0; kk < BK; kk++) {
            float a[8], b[8];
            *(float4*)&a[0] = *(const float4*)&As[kk][ty * 8];
            *(float4*)&a[4] = *(const float4*)&As[kk][ty * 8 + 4];
            *(float4*)&b[0] = *(const float4*)&Bs[kk][tx * 8];
            *(float4*)&b[4] = *(const float4*)&Bs[kk][tx * 8 + 4];
            #pragma unroll
            for (int i = 0; i < 8; i++)
                #pragma unroll
                for (int j = 0; j < 8; j++)
                    acc[i][j] = fmaf(a[i], b[j], acc[i][j]);
        }
        __syncthreads();
    }

    #pragma unroll
    for (int i = 0; i < 8; i++) {
        int m = m0 + ty * 8 + i;
        #pragma unroll
        for (int j = 0; j < 8; j++) {
            int n = n0 + tx * 8 + j;
            if (n < N) {
                float v = acc[i][j];
                if (EPI == 1) v = softplusf(v + bias[n]);
                if (EPI == 2) v = v + res[(size_t)m * ldc + n];
                C[(size_t)m * ldc + n] = v;
            }
        }
    }
}

// ---------------- causal depthwise conv (k=4) + silu ------------------------
__global__ void conv_silu_kernel(const float* __restrict__ xz,
                                 const float* __restrict__ cw,
                                 const float* __restrict__ cb,
                                 float* __restrict__ xc)
{
    int idx = blockIdx.x * blockDim.x + threadIdx.x;
    if (idx >= LSEQ * DI) return;
    int l = idx / DI;
    int e = idx - l * DI;
    float acc = cb[e];
    #pragma unroll
    for (int k = 0; k < 4; k++) {
        int ls = l + k - 3;
        if (ls >= 0) acc = fmaf(xz[(size_t)ls * (2 * DI) + e], cw[e * 4 + k], acc);
    }
    xc[idx] = siluf(acc);
}

// ---------------- selective scan + D-skip + silu(z) gate --------------------
// 16 threads per channel (one per state n). 256 thr/block -> 16 channels.
__global__ void __launch_bounds__(256) scan_kernel(
    const float* __restrict__ dbl,   // [L,96] : [.. | B(16) | C(16)]
    const float* __restrict__ dtf,   // [L,E]
    const float* __restrict__ xz,    // [L,2E] (z part used)
    const float* __restrict__ xc,    // [L,E]
    const float* __restrict__ A_log, // [E,16]
    const float* __restrict__ Dp,    // [E]
    float* __restrict__ y)           // [L,E]
{
    int t = threadIdx.x;
    int n = t & 15;
    int e = blockIdx.x * 16 + (t >> 4);

    float Aen = -__expf(A_log[e * DS + n]);
    float Dv  = Dp[e];
    float h   = 0.f;

    const float* pB = dbl + DTR + n;
    const float* pC = dbl + DTR + DS + n;

    for (int l = 0; l < LSEQ; l++) {
        float dt  = dtf[(size_t)l * DI + e];
        float xcv = xc [(size_t)l * DI + e];
        float Bv  = pB[(size_t)l * DBLC];
        float Cv  = pC[(size_t)l * DBLC];
        float dA  = __expf(dt * Aen);
        h = fmaf(dA, h, dt * xcv * Bv);
        float p = h * Cv;
        p += __shfl_xor_sync(0xffffffffu, p, 8);
        p += __shfl_xor_sync(0xffffffffu, p, 4);
        p += __shfl_xor_sync(0xffffffffu, p, 2);
        p += __shfl_xor_sync(0xffffffffu, p, 1);
        if (n == 0) {
            float zv = xz[(size_t)l * (2 * DI) + DI + e];
            float yv = p + xcv * Dv;
            y[(size_t)l * DI + e] = yv * siluf(zv);
        }
    }
}

// ---------------- launch ----------------------------------------------------
extern "C" void kernel_launch(void* const* d_in, const int* in_sizes, int n_in,
                              void* d_out, int out_size)
{
    const float* x_in  = (const float*)d_in[0];
    const float* ln_w  = (const float*)d_in[1];
    const float* ln_b  = (const float*)d_in[2];
    const float* inw   = (const float*)d_in[3];
    const float* cw    = (const float*)d_in[4];
    const float* cb    = (const float*)d_in[5];
    const float* xpw   = (const float*)d_in[6];
    const float* dtw   = (const float*)d_in[7];
    const float* dtb   = (const float*)d_in[8];
    const float* alog  = (const float*)d_in[9];
    const float* dskip = (const float*)d_in[10];
    const float* outw  = (const float*)d_in[11];
    const float* nfw   = (const float*)d_in[12];
    const float* nfb   = (const float*)d_in[13];
    float* out = (float*)d_out;

    float *px, *ph, *pxz, *pxc, *pdbl, *pdt, *py;
    cudaGetSymbolAddress((void**)&px,  g_x);
    cudaGetSymbolAddress((void**)&ph,  g_h);
    cudaGetSymbolAddress((void**)&pxz, g_xz);
    cudaGetSymbolAddress((void**)&pxc, g_xc);
    cudaGetSymbolAddress((void**)&pdbl,g_dbl);
    cudaGetSymbolAddress((void**)&pdt, g_dt);
    cudaGetSymbolAddress((void**)&py,  g_y);

    // residual stream <- input
    copy_kernel<<<(LSEQ * DM + 255) / 256, 256>>>(x_in, px, LSEQ * DM);

    for (int i = 0; i < 2; i++) {
        // 1) layernorm
        ln_kernel<<<LSEQ, 256>>>(px, ln_w + i * DM, ln_b + i * DM, ph);

        // 2) in_proj: [L,4096] = h[L,1024] @ W[4096,1024]^T
        gemm_nt<0><<<dim3(2 * DI / 128, LSEQ / 128), 256>>>(
            ph, DM, inw + (size_t)i * 2 * DI * DM, DM,
            pxz, 2 * DI, 2 * DI, DM, nullptr, nullptr);

        // 3) causal conv + silu
        conv_silu_kernel<<<(LSEQ * DI + 255) / 256, 256>>>(
            pxz, cw + (size_t)i * DI * 4, cb + (size_t)i * DI, pxc);

        // 4) x_proj: [L,96] = xc[L,2048] @ W[96,2048]^T
        gemm_nt<0><<<dim3(1, LSEQ / 128), 256>>>(
            pxc, DI, xpw + (size_t)i * DBLC * DI, DI,
            pdbl, DBLC, DBLC, DI, nullptr, nullptr);

        // 5) dt_proj + bias + softplus: [L,2048] = dbl[:, :64] @ W[2048,64]^T
        gemm_nt<1><<<dim3(DI / 128, LSEQ / 128), 256>>>(
            pdbl, DBLC, dtw + (size_t)i * DI * DTR, DTR,
            pdt, DI, DI, DTR, dtb + (size_t)i * DI, nullptr);

        // 6) selective scan + skip + gate
        scan_kernel<<<DI / 16, 256>>>(
            pdbl, pdt, pxz, pxc,
            alog + (size_t)i * DI * DS, dskip + (size_t)i * DI, py);

        // 7) out_proj + residual: x = x + y[L,2048] @ W[1024,2048]^T
        gemm_nt<2><<<dim3(DM / 128, LSEQ / 128), 256>>>(
            py, DI, outw + (size_t)i * DM * DI, DI,
            px, DM, DM, DI, nullptr, px);
    }

    // final layernorm -> output
    ln_kernel<<<LSEQ, 256>>>(px, nfw, nfb, out);
}

// round 3
// speedup vs baseline: 1.2395x; 1.2395x over previous
#include <cuda_runtime.h>
#include <cuda_bf16.h>
#include <math.h>
#include <stdint.h>

#define LSEQ 2048
#define DM   1024
#define DI   2048
#define DS   16
#define DTR  64
#define DBLC 96   /* DTR + 2*DS */

// ======================= static scratch (no allocation) ======================
__device__ float g_x  [LSEQ * DM];        // residual stream (fp32)
__device__ float g_xz [LSEQ * 2 * DI];    // in_proj out [xc | z]
__device__ float g_xc [LSEQ * DI];        // conv+silu (fp32, for scan)
__device__ float g_dbl[LSEQ * DBLC];      // x_proj out
__device__ float g_dt [LSEQ * DI];        // softplus(dt_proj)

// split-bf16 activation buffers
__device__ __align__(16) __nv_bfloat16 g_h_h  [LSEQ * DM];
__device__ __align__(16) __nv_bfloat16 g_h_l  [LSEQ * DM];
__device__ __align__(16) __nv_bfloat16 g_xc_h [LSEQ * DI];
__device__ __align__(16) __nv_bfloat16 g_xc_l [LSEQ * DI];
__device__ __align__(16) __nv_bfloat16 g_y_h  [LSEQ * DI];
__device__ __align__(16) __nv_bfloat16 g_y_l  [LSEQ * DI];
__device__ __align__(16) __nv_bfloat16 g_da_h [LSEQ * DTR];
__device__ __align__(16) __nv_bfloat16 g_da_l [LSEQ * DTR];

// split-bf16 weights (both layers contiguous)
__device__ __align__(16) __nv_bfloat16 g_inw_h[2 * 2 * DI * DM];
__device__ __align__(16) __nv_bfloat16 g_inw_l[2 * 2 * DI * DM];
__device__ __align__(16) __nv_bfloat16 g_xpw_h[2 * DBLC * DI];
__device__ __align__(16) __nv_bfloat16 g_xpw_l[2 * DBLC * DI];
__device__ __align__(16) __nv_bfloat16 g_dtw_h[2 * DI * DTR];
__device__ __align__(16) __nv_bfloat16 g_dtw_l[2 * DI * DTR];
__device__ __align__(16) __nv_bfloat16 g_otw_h[2 * DM * DI];
__device__ __align__(16) __nv_bfloat16 g_otw_l[2 * DM * DI];

// ======================= helpers =============================================
__device__ __forceinline__ float siluf(float x) { return x / (1.0f + __expf(-x)); }
__device__ __forceinline__ float softplusf(float x) {
    if (x > 20.0f) return x;
    return log1pf(__expf(x));
}
__device__ __forceinline__ void split_bf16(float v, __nv_bfloat16& h, __nv_bfloat16& l) {
    h = __float2bfloat16(v);
    l = __float2bfloat16(v - __bfloat162float(h));
}
__device__ __forceinline__ uint32_t smem_u32(const void* p) {
    uint32_t a;
    asm("{ .reg .u64 t; cvta.to.shared.u64 t, %1; cvt.u32.u64 %0, t; }" : "=r"(a) : "l"(p));
    return a;
}

__device__ __forceinline__ void cpa16(uint32_t d, const void* s, int sz) {
    asm volatile("cp.async.cg.shared.global [%0], [%1], 16, %2;" :: "r"(d), "l"(s), "r"(sz) : "memory");
}
#define CP_COMMIT() asm volatile("cp.async.commit_group;" ::: "memory")
#define CP_WAIT(n)  asm volatile("cp.async.wait_group %0;" :: "n"(n) : "memory")

#define LDSM4(r0, r1, r2, r3, addr)                                            \
    asm volatile("ldmatrix.sync.aligned.m8n8.x4.shared.b16 {%0,%1,%2,%3}, [%4];" \
        : "=r"(r0), "=r"(r1), "=r"(r2), "=r"(r3) : "r"(addr))

#define MMA16816(d, a, b)                                                      \
    asm volatile("mma.sync.aligned.m16n8k16.row.col.f32.bf16.bf16.f32 "        \
        "{%0,%1,%2,%3},{%4,%5,%6,%7},{%8,%9},{%0,%1,%2,%3};"                   \
        : "+f"((d)[0]), "+f"((d)[1]), "+f"((d)[2]), "+f"((d)[3])               \
        : "r"((a)[0]), "r"((a)[1]), "r"((a)[2]), "r"((a)[3]),                  \
          "r"((b)[0]), "r"((b)[1]))

// ======================= HMMA GEMM ===========================================
// C[m,n] = sum_k A[m,k]*B[n,k], split-bf16 (3 passes).
// BM=BN=128, BK=32, 8 warps (4m x 2n), warp tile 32x64, double-buffered cp.async.
// Smem per stage: Ahi 8K | Alo 8K | Bhi 8K | Blo 8K = 32K; 2 stages = 64K.
// EPI 0: store fp32; 1: softplus(acc+bias[n]); 2: acc + C (in-place residual)

#define STG_BYTES 32768
#define OFF_ALO   8192
#define OFF_BHI   16384
#define OFF_BLO   24576

__device__ __forceinline__ void stage_load(
    uint32_t sbase,
    const __nv_bfloat16* __restrict__ Ah, const __nv_bfloat16* __restrict__ Al,
    const __nv_bfloat16* __restrict__ Bh, const __nv_bfloat16* __restrict__ Bl,
    int m0, int n0, int k0, int K, int Nmat, int tid)
{
    #pragma unroll
    for (int it = 0; it < 2; it++) {
        int id   = tid + it * 256;       // 0..511
        int r    = id >> 2;              // 0..127
        int slot = id & 3;               // 16B slot within 64B row
        uint32_t so = (uint32_t)(r * 64 + ((slot ^ ((r >> 1) & 3)) << 4));
        size_t ga = (size_t)(m0 + r) * K + k0 + slot * 8;
        cpa16(sbase + so,           Ah + ga, 16);
        cpa16(sbase + OFF_ALO + so, Al + ga, 16);
        int nrow = n0 + r;
        bool ok  = nrow < Nmat;
        size_t gb = (size_t)(ok ? nrow : 0) * K + k0 + slot * 8;
        cpa16(sbase + OFF_BHI + so, Bh + gb, ok ? 16 : 0);
        cpa16(sbase + OFF_BLO + so, Bl + gb, ok ? 16 : 0);
    }
}

template<int EPI>
__global__ void __launch_bounds__(256) gemm_mma(
    const __nv_bfloat16* __restrict__ Ah, const __nv_bfloat16* __restrict__ Al,
    const __nv_bfloat16* __restrict__ Bh, const __nv_bfloat16* __restrict__ Bl,
    float* __restrict__ C, int ldc, int Nmat, int K,
    const float* __restrict__ bias)
{
    extern __shared__ char smem[];
    const uint32_t sb = smem_u32(smem);
    const int tid  = threadIdx.x;
    const int lane = tid & 31;
    const int wid  = tid >> 5;
    const int m0   = blockIdx.y * 128;
    const int n0   = blockIdx.x * 128;
    const int wm   = (wid & 3) * 32;    // warp m offset in tile
    const int wn   = (wid >> 2) * 64;   // warp n offset in tile

    // precompute ldmatrix lane offsets (ks = 0); ks = 1 toggles ^0x20
    uint32_t aoff[2], boff[4];
    {
        int mat = lane >> 3, row = lane & 7;
        #pragma unroll
        for (int mf = 0; mf < 2; mf++) {
            int r = wm + mf * 16 + ((mat & 1) << 3) + row;
            int slot = mat >> 1;
            aoff[mf] = (uint32_t)(r * 64 + ((slot ^ ((r >> 1) & 3)) << 4));
        }
        #pragma unroll
        for (int p = 0; p < 4; p++) {
            int n = wn + p * 16 + ((mat >> 1) << 3) + row;
            int slot = mat & 1;
            boff[p] = (uint32_t)(n * 64 + ((slot ^ ((n >> 1) & 3)) << 4));
        }
    }

    float acc[2][8][4];
    #pragma unroll
    for (int i = 0; i < 2; i++)
        #pragma unroll
        for (int j = 0; j < 8; j++)
            #pragma unroll
            for (int q = 0; q < 4; q++) acc[i][j][q] = 0.f;

    const int nsteps = K >> 5;

    stage_load(sb, Ah, Al, Bh, Bl, m0, n0, 0, K, Nmat, tid);
    CP_COMMIT();

    for (int s = 0; s < nsteps; s++) {
        if (s + 1 < nsteps) {
            stage_load(sb + ((s + 1) & 1) * STG_BYTES, Ah, Al, Bh, Bl,
                       m0, n0, (s + 1) << 5, K, Nmat, tid);
            CP_COMMIT();
            CP_WAIT(1);
        } else {
            CP_WAIT(0);
        }
        __syncthreads();

        const uint32_t base = sb + (s & 1) * STG_BYTES;
        #pragma unroll
        for (int ks = 0; ks < 2; ks++) {
            const uint32_t kx = ks ? 0x20u : 0u;
            uint32_t ah[2][4], al[2][4], bh[8][2], bl[8][2];
            #pragma unroll
            for (int mf = 0; mf < 2; mf++) {
                LDSM4(ah[mf][0], ah[mf][1], ah[mf][2], ah[mf][3], base + (aoff[mf] ^ kx));
                LDSM4(al[mf][0], al[mf][1], al[mf][2], al[mf][3], base + OFF_ALO + (aoff[mf] ^ kx));
            }
            #pragma unroll
            for (int p = 0; p < 4; p++) {
                LDSM4(bh[2*p][0], bh[2*p][1], bh[2*p+1][0], bh[2*p+1][1],
                      base + OFF_BHI + (boff[p] ^ kx));
                LDSM4(bl[2*p][0], bl[2*p][1], bl[2*p+1][0], bl[2*p+1][1],
                      base + OFF_BLO + (boff[p] ^ kx));
            }
            #pragma unroll
            for (int mf = 0; mf < 2; mf++)
                #pragma unroll
                for (int nf = 0; nf < 8; nf++) {
                    MMA16816(acc[mf][nf], ah[mf], bh[nf]);
                    MMA16816(acc[mf][nf], ah[mf], bl[nf]);
                    MMA16816(acc[mf][nf], al[mf], bh[nf]);
                }
        }
        __syncthreads();
    }

    // ---------------- epilogue ----------------
    const int mrow = m0 + wm + (lane >> 2);
    const int ncol = n0 + wn + (lane & 3) * 2;
    #pragma unroll
    for (int mf = 0; mf < 2; mf++) {
        #pragma unroll
        for (int nf = 0; nf < 8; nf++) {
            const int n = ncol + nf * 8;
            #pragma unroll
            for (int half = 0; half < 2; half++) {
                const int m = mrow + mf * 16 + half * 8;
                #pragma unroll
                for (int j = 0; j < 2; j++) {
                    const int nn = n + j;
                    if (nn < Nmat) {
                        float v = acc[mf][nf][half * 2 + j];
                        if (EPI == 1) v = softplusf(v + bias[nn]);
                        if (EPI == 2) v = v + C[(size_t)m * ldc + nn];
                        C[(size_t)m * ldc + nn] = v;
                    }
                }
            }
        }
    }
}

// ======================= misc kernels ========================================
__global__ void copy_kernel(const float* __restrict__ s, float* __restrict__ d, int n) {
    int i = blockIdx.x * blockDim.x + threadIdx.x;
    if (i < n) d[i] = s[i];
}

__global__ void convert_split_kernel(const float* __restrict__ s,
                                     __nv_bfloat16* __restrict__ h,
                                     __nv_bfloat16* __restrict__ l, int n) {
    int i = blockIdx.x * blockDim.x + threadIdx.x;
    if (i < n) { __nv_bfloat16 hv, lv; split_bf16(s[i], hv, lv); h[i] = hv; l[i] = lv; }
}

// extract dbl[:, :64] -> split bf16 [L,64]
__global__ void dbla_kernel(const float* __restrict__ dbl,
                            __nv_bfloat16* __restrict__ h, __nv_bfloat16* __restrict__ l) {
    int i = blockIdx.x * blockDim.x + threadIdx.x;
    if (i >= LSEQ * DTR) return;
    int row = i >> 6, c = i & 63;
    __nv_bfloat16 hv, lv;
    split_bf16(dbl[row * DBLC + c], hv, lv);
    h[i] = hv; l[i] = lv;
}

// layernorm -> split bf16 (BF=1) or fp32 (BF=0)
template<int BF>
__global__ void __launch_bounds__(256) ln_kernel(
    const float* __restrict__ x, const float* __restrict__ w, const float* __restrict__ b,
    float* __restrict__ outf, __nv_bfloat16* __restrict__ oh, __nv_bfloat16* __restrict__ ol)
{
    int row = blockIdx.x, t = threadIdx.x;
    const float* xr = x + row * DM;
    float4 v = *(const float4*)(xr + t * 4);
    float s  = v.x + v.y + v.z + v.w;
    float ss = v.x * v.x + v.y * v.y + v.z * v.z + v.w * v.w;
    #pragma unroll
    for (int o = 16; o; o >>= 1) {
        s  += __shfl_xor_sync(0xffffffffu, s,  o);
        ss += __shfl_xor_sync(0xffffffffu, ss, o);
    }
    __shared__ float sr[8], sq[8], smu, srs;
    int wid = t >> 5, lane = t & 31;
    if (lane == 0) { sr[wid] = s; sq[wid] = ss; }
    __syncthreads();
    if (t == 0) {
        float S = 0.f, SS = 0.f;
        #pragma unroll
        for (int i = 0; i < 8; i++) { S += sr[i]; SS += sq[i]; }
        float mu = S * (1.0f / DM);
        smu = mu; srs = rsqrtf(SS * (1.0f / DM) - mu * mu + 1e-5f);
    }
    __syncthreads();
    float mu = smu, rs = srs;
    float4 wv = *(const float4*)(w + t * 4);
    float4 bv = *(const float4*)(b + t * 4);
    float o0 = (v.x - mu) * rs * wv.x + bv.x;
    float o1 = (v.y - mu) * rs * wv.y + bv.y;
    float o2 = (v.z - mu) * rs * wv.z + bv.z;
    float o3 = (v.w - mu) * rs * wv.w + bv.w;
    size_t base = (size_t)row * DM + t * 4;
    if (BF) {
        __nv_bfloat16 hh, ll;
        split_bf16(o0, hh, ll); oh[base + 0] = hh; ol[base + 0] = ll;
        split_bf16(o1, hh, ll); oh[base + 1] = hh; ol[base + 1] = ll;
        split_bf16(o2, hh, ll); oh[base + 2] = hh; ol[base + 2] = ll;
        split_bf16(o3, hh, ll); oh[base + 3] = hh; ol[base + 3] = ll;
    } else {
        float4 o4; o4.x = o0; o4.y = o1; o4.z = o2; o4.w = o3;
        *(float4*)(outf + base) = o4;
    }
}

// causal depthwise conv(k=4) + silu -> fp32 + split bf16
__global__ void conv_silu_kernel(const float* __restrict__ xz,
                                 const float* __restrict__ cw, const float* __restrict__ cb,
                                 float* __restrict__ xc,
                                 __nv_bfloat16* __restrict__ xch, __nv_bfloat16* __restrict__ xcl)
{
    int idx = blockIdx.x * blockDim.x + threadIdx.x;
    if (idx >= LSEQ * DI) return;
    int l = idx / DI, e = idx - l * DI;
    float acc = cb[e];
    #pragma unroll
    for (int k = 0; k < 4; k++) {
        int ls = l + k - 3;
        if (ls >= 0) acc = fmaf(xz[(size_t)ls * (2 * DI) + e], cw[e * 4 + k], acc);
    }
    float v = siluf(acc);
    xc[idx] = v;
    __nv_bfloat16 hh, ll;
    split_bf16(v, hh, ll);
    xch[idx] = hh; xcl[idx] = ll;
}

// selective scan + D-skip + silu(z) gate -> split bf16 y
__global__ void __launch_bounds__(256) scan_kernel(
    const float* __restrict__ dbl, const float* __restrict__ dtf,
    const float* __restrict__ xz, const float* __restrict__ xc,
    const float* __restrict__ A_log, const float* __restrict__ Dp,
    __nv_bfloat16* __restrict__ yh, __nv_bfloat16* __restrict__ yl)
{
    int t = threadIdx.x;
    int n = t & 15;
    int e = blockIdx.x * 16 + (t >> 4);

    float Aen = -__expf(A_log[e * DS + n]);
    float Dv  = Dp[e];
    float h   = 0.f;
    const float* pB = dbl + DTR + n;
    const float* pC = dbl + DTR + DS + n;

    for (int l = 0; l < LSEQ; l++) {
        float dt  = dtf[(size_t)l * DI + e];
        float xcv = xc [(size_t)l * DI + e];
        float Bv  = pB[(size_t)l * DBLC];
        float Cv  = pC[(size_t)l * DBLC];
        float dA  = __expf(dt * Aen);
        h = fmaf(dA, h, dt * xcv * Bv);
        float p = h * Cv;
        p += __shfl_xor_sync(0xffffffffu, p, 8);
        p += __shfl_xor_sync(0xffffffffu, p, 4);
        p += __shfl_xor_sync(0xffffffffu, p, 2);
        p += __shfl_xor_sync(0xffffffffu, p, 1);
        if (n == 0) {
            float zv = xz[(size_t)l * (2 * DI) + DI + e];
            float yv = (p + xcv * Dv) * siluf(zv);
            __nv_bfloat16 hh, ll;
            split_bf16(yv, hh, ll);
            yh[(size_t)l * DI + e] = hh;
            yl[(size_t)l * DI + e] = ll;
        }
    }
}

// ======================= launch ==============================================
extern "C" void kernel_launch(void* const* d_in, const int* in_sizes, int n_in,
                              void* d_out, int out_size)
{
    const float* x_in  = (const float*)d_in[0];
    const float* ln_w  = (const float*)d_in[1];
    const float* ln_b  = (const float*)d_in[2];
    const float* inw   = (const float*)d_in[3];
    const float* cw    = (const float*)d_in[4];
    const float* cb    = (const float*)d_in[5];
    const float* xpw   = (const float*)d_in[6];
    const float* dtw   = (const float*)d_in[7];
    const float* dtb   = (const float*)d_in[8];
    const float* alog  = (const float*)d_in[9];
    const float* dskip = (const float*)d_in[10];
    const float* outw  = (const float*)d_in[11];
    const float* nfw   = (const float*)d_in[12];
    const float* nfb   = (const float*)d_in[13];
    float* out = (float*)d_out;

    float *px, *pxz, *pxc, *pdbl, *pdt;
    __nv_bfloat16 *phh, *phl, *pxch, *pxcl, *pyh, *pyl, *pdah, *pdal;
    __nv_bfloat16 *winh, *winl, *wxph, *wxpl, *wdth, *wdtl, *woth, *wotl;
    cudaGetSymbolAddress((void**)&px,   g_x);
    cudaGetSymbolAddress((void**)&pxz,  g_xz);
    cudaGetSymbolAddress((void**)&pxc,  g_xc);
    cudaGetSymbolAddress((void**)&pdbl, g_dbl);
    cudaGetSymbolAddress((void**)&pdt,  g_dt);
    cudaGetSymbolAddress((void**)&phh,  g_h_h);
    cudaGetSymbolAddress((void**)&phl,  g_h_l);
    cudaGetSymbolAddress((void**)&pxch, g_xc_h);
    cudaGetSymbolAddress((void**)&pxcl, g_xc_l);
    cudaGetSymbolAddress((void**)&pyh,  g_y_h);
    cudaGetSymbolAddress((void**)&pyl,  g_y_l);
    cudaGetSymbolAddress((void**)&pdah, g_da_h);
    cudaGetSymbolAddress((void**)&pdal, g_da_l);
    cudaGetSymbolAddress((void**)&winh, g_inw_h);
    cudaGetSymbolAddress((void**)&winl, g_inw_l);
    cudaGetSymbolAddress((void**)&wxph, g_xpw_h);
    cudaGetSymbolAddress((void**)&wxpl, g_xpw_l);
    cudaGetSymbolAddress((void**)&wdth, g_dtw_h);
    cudaGetSymbolAddress((void**)&wdtl, g_dtw_l);
    cudaGetSymbolAddress((void**)&woth, g_otw_h);
    cudaGetSymbolAddress((void**)&wotl, g_otw_l);

    cudaFuncSetAttribute(gemm_mma<0>, cudaFuncAttributeMaxDynamicSharedMemorySize, 2 * STG_BYTES);
    cudaFuncSetAttribute(gemm_mma<1>, cudaFuncAttributeMaxDynamicSharedMemorySize, 2 * STG_BYTES);
    cudaFuncSetAttribute(gemm_mma<2>, cudaFuncAttributeMaxDynamicSharedMemorySize, 2 * STG_BYTES);

    // residual stream <- input; weight splits
    copy_kernel<<<(LSEQ * DM + 255) / 256, 256>>>(x_in, px, LSEQ * DM);
    { int n = 2 * 2 * DI * DM; convert_split_kernel<<<(n + 255) / 256, 256>>>(inw,  winh, winl, n); }
    { int n = 2 * DBLC * DI;   convert_split_kernel<<<(n + 255) / 256, 256>>>(xpw,  wxph, wxpl, n); }
    { int n = 2 * DI * DTR;    convert_split_kernel<<<(n + 255) / 256, 256>>>(dtw,  wdth, wdtl, n); }
    { int n = 2 * DM * DI;     convert_split_kernel<<<(n + 255) / 256, 256>>>(outw, woth, wotl, n); }

    for (int i = 0; i < 2; i++) {
        // 1) layernorm -> split bf16 h
        ln_kernel<1><<<LSEQ, 256>>>(px, ln_w + i * DM, ln_b + i * DM, nullptr, phh, phl);

        // 2) in_proj: [L,4096] = h @ inw^T  (K=1024)
        gemm_mma<0><<<dim3(2 * DI / 128, LSEQ / 128), 256, 2 * STG_BYTES>>>(
            phh, phl, winh + (size_t)i * 2 * DI * DM, winl + (size_t)i * 2 * DI * DM,
            pxz, 2 * DI, 2 * DI, DM, nullptr);

        // 3) conv + silu
        conv_silu_kernel<<<(LSEQ * DI + 255) / 256, 256>>>(
            pxz, cw + (size_t)i * DI * 4, cb + (size_t)i * DI, pxc, pxch, pxcl);

        // 4) x_proj: [L,96] = xc @ xpw^T (K=2048)
        gemm_mma<0><<<dim3(1, LSEQ / 128), 256, 2 * STG_BYTES>>>(
            pxch, pxcl, wxph + (size_t)i * DBLC * DI, wxpl + (size_t)i * DBLC * DI,
            pdbl, DBLC, DBLC, DI, nullptr);

        // 5) extract dt_lr -> split bf16
        dbla_kernel<<<(LSEQ * DTR + 255) / 256, 256>>>(pdbl, pdah, pdal);

        // 6) dt_proj + softplus: [L,2048] (K=64)
        gemm_mma<1><<<dim3(DI / 128, LSEQ / 128), 256, 2 * STG_BYTES>>>(
            pdah, pdal, wdth + (size_t)i * DI * DTR, wdtl + (size_t)i * DI * DTR,
            pdt, DI, DI, DTR, dtb + (size_t)i * DI);

        // 7) selective scan -> split bf16 y
        scan_kernel<<<DI / 16, 256>>>(
            pdbl, pdt, pxz, pxc,
            alog + (size_t)i * DI * DS, dskip + (size_t)i * DI, pyh, pyl);

        // 8) out_proj + residual (K=2048)
        gemm_mma<2><<<dim3(DM / 128, LSEQ / 128), 256, 2 * STG_BYTES>>>(
            pyh, pyl, woth + (size_t)i * DM * DI, wotl + (size_t)i * DM * DI,
            px, DM, DM, DI, nullptr);
    }

    // final layernorm -> fp32 output
    ln_kernel<0><<<LSEQ, 256>>>(px, nfw, nfb, out, nullptr, nullptr);
}

// round 4
// speedup vs baseline: 3.4363x; 2.7723x over previous
#include <cuda_runtime.h>
#include <cuda_bf16.h>
#include <math.h>
#include <stdint.h>

#define LSEQ 2048
#define DM   1024
#define DI   2048
#define DS   16
#define DTR  64
#define DBLC 96   /* DTR + 2*DS */

// ======================= static scratch (no allocation) ======================
__device__ float g_x  [LSEQ * DM];        // residual stream (fp32)
__device__ float g_xz [LSEQ * 2 * DI];    // in_proj out [xc | z]
__device__ float g_xc [LSEQ * DI];        // conv+silu (fp32, for scan)
__device__ float g_dbl[LSEQ * DBLC];      // x_proj out
__device__ float g_dt [LSEQ * DI];        // softplus(dt_proj)

// split-bf16 activation buffers
__device__ __align__(16) __nv_bfloat16 g_h_h  [LSEQ * DM];
__device__ __align__(16) __nv_bfloat16 g_h_l  [LSEQ * DM];
__device__ __align__(16) __nv_bfloat16 g_xc_h [LSEQ * DI];
__device__ __align__(16) __nv_bfloat16 g_xc_l [LSEQ * DI];
__device__ __align__(16) __nv_bfloat16 g_y_h  [LSEQ * DI];
__device__ __align__(16) __nv_bfloat16 g_y_l  [LSEQ * DI];
__device__ __align__(16) __nv_bfloat16 g_da_h [LSEQ * DTR];
__device__ __align__(16) __nv_bfloat16 g_da_l [LSEQ * DTR];

// split-bf16 weights (both layers contiguous)
__device__ __align__(16) __nv_bfloat16 g_inw_h[2 * 2 * DI * DM];
__device__ __align__(16) __nv_bfloat16 g_inw_l[2 * 2 * DI * DM];
__device__ __align__(16) __nv_bfloat16 g_xpw_h[2 * DBLC * DI];
__device__ __align__(16) __nv_bfloat16 g_xpw_l[2 * DBLC * DI];
__device__ __align__(16) __nv_bfloat16 g_dtw_h[2 * DI * DTR];
__device__ __align__(16) __nv_bfloat16 g_dtw_l[2 * DI * DTR];
__device__ __align__(16) __nv_bfloat16 g_otw_h[2 * DM * DI];
__device__ __align__(16) __nv_bfloat16 g_otw_l[2 * DM * DI];

// ======================= helpers =============================================
__device__ __forceinline__ float siluf(float x) { return x / (1.0f + __expf(-x)); }
__device__ __forceinline__ float softplusf(float x) {
    if (x > 20.0f) return x;
    return log1pf(__expf(x));
}
__device__ __forceinline__ void split_bf16(float v, __nv_bfloat16& h, __nv_bfloat16& l) {
    h = __float2bfloat16(v);
    l = __float2bfloat16(v - __bfloat162float(h));
}
__device__ __forceinline__ uint32_t smem_u32(const void* p) {
    uint32_t a;
    asm("{ .reg .u64 t; cvta.to.shared.u64 t, %1; cvt.u32.u64 %0, t; }" : "=r"(a) : "l"(p));
    return a;
}

__device__ __forceinline__ void cpa16(uint32_t d, const void* s, int sz) {
    asm volatile("cp.async.cg.shared.global [%0], [%1], 16, %2;" :: "r"(d), "l"(s), "r"(sz) : "memory");
}
__device__ __forceinline__ void cpa16f(uint32_t d, const void* s) {
    asm volatile("cp.async.cg.shared.global [%0], [%1], 16;" :: "r"(d), "l"(s) : "memory");
}
#define CP_COMMIT() asm volatile("cp.async.commit_group;" ::: "memory")
#define CP_WAIT(n)  asm volatile("cp.async.wait_group %0;" :: "n"(n) : "memory")

#define LDSM4(r0, r1, r2, r3, addr)                                            \
    asm volatile("ldmatrix.sync.aligned.m8n8.x4.shared.b16 {%0,%1,%2,%3}, [%4];" \
        : "=r"(r0), "=r"(r1), "=r"(r2), "=r"(r3) : "r"(addr))

#define MMA16816(d, a, b)                                                      \
    asm volatile("mma.sync.aligned.m16n8k16.row.col.f32.bf16.bf16.f32 "        \
        "{%0,%1,%2,%3},{%4,%5,%6,%7},{%8,%9},{%0,%1,%2,%3};"                   \
        : "+f"((d)[0]), "+f"((d)[1]), "+f"((d)[2]), "+f"((d)[3])               \
        : "r"((a)[0]), "r"((a)[1]), "r"((a)[2]), "r"((a)[3]),                  \
          "r"((b)[0]), "r"((b)[1]))

// ======================= HMMA GEMM ===========================================
// C[m,n] = sum_k A[m,k]*B[n,k], split-bf16 (3 passes).
// BM=BN=128, BK=32, 8 warps (4m x 2n), warp tile 32x64, double-buffered cp.async.
// EPI 0: store fp32; 1: softplus(acc+bias[n]); 2: acc + C (in-place residual)

#define STG_BYTES 32768
#define OFF_ALO   8192
#define OFF_BHI   16384
#define OFF_BLO   24576

__device__ __forceinline__ void stage_load(
    uint32_t sbase,
    const __nv_bfloat16* __restrict__ Ah, const __nv_bfloat16* __restrict__ Al,
    const __nv_bfloat16* __restrict__ Bh, const __nv_bfloat16* __restrict__ Bl,
    int m0, int n0, int k0, int K, int Nmat, int tid)
{
    #pragma unroll
    for (int it = 0; it < 2; it++) {
        int id   = tid + it * 256;       // 0..511
        int r    = id >> 2;              // 0..127
        int slot = id & 3;               // 16B slot within 64B row
        uint32_t so = (uint32_t)(r * 64 + ((slot ^ ((r >> 1) & 3)) << 4));
        size_t ga = (size_t)(m0 + r) * K + k0 + slot * 8;
        cpa16(sbase + so,           Ah + ga, 16);
        cpa16(sbase + OFF_ALO + so, Al + ga, 16);
        int nrow = n0 + r;
        bool ok  = nrow < Nmat;
        size_t gb = (size_t)(ok ? nrow : 0) * K + k0 + slot * 8;
        cpa16(sbase + OFF_BHI + so, Bh + gb, ok ? 16 : 0);
        cpa16(sbase + OFF_BLO + so, Bl + gb, ok ? 16 : 0);
    }
}

template<int EPI>
__global__ void __launch_bounds__(256) gemm_mma(
    const __nv_bfloat16* __restrict__ Ah, const __nv_bfloat16* __restrict__ Al,
    const __nv_bfloat16* __restrict__ Bh, const __nv_bfloat16* __restrict__ Bl,
    float* __restrict__ C, int ldc, int Nmat, int K,
    const float* __restrict__ bias)
{
    extern __shared__ char smem[];
    const uint32_t sb = smem_u32(smem);
    const int tid  = threadIdx.x;
    const int lane = tid & 31;
    const int wid  = tid >> 5;
    const int m0   = blockIdx.y * 128;
    const int n0   = blockIdx.x * 128;
    const int wm   = (wid & 3) * 32;    // warp m offset in tile
    const int wn   = (wid >> 2) * 64;   // warp n offset in tile

    // precompute ldmatrix lane offsets (ks = 0); ks = 1 toggles ^0x20
    uint32_t aoff[2], boff[4];
    {
        int mat = lane >> 3, row = lane & 7;
        #pragma unroll
        for (int mf = 0; mf < 2; mf++) {
            int r = wm + mf * 16 + ((mat & 1) << 3) + row;
            int slot = mat >> 1;
            aoff[mf] = (uint32_t)(r * 64 + ((slot ^ ((r >> 1) & 3)) << 4));
        }
        #pragma unroll
        for (int p = 0; p < 4; p++) {
            int n = wn + p * 16 + ((mat >> 1) << 3) + row;
            int slot = mat & 1;
            boff[p] = (uint32_t)(n * 64 + ((slot ^ ((n >> 1) & 3)) << 4));
        }
    }

    float acc[2][8][4];
    #pragma unroll
    for (int i = 0; i < 2; i++)
        #pragma unroll
        for (int j = 0; j < 8; j++)
            #pragma unroll
            for (int q = 0; q < 4; q++) acc[i][j][q] = 0.f;

    const int nsteps = K >> 5;

    stage_load(sb, Ah, Al, Bh, Bl, m0, n0, 0, K, Nmat, tid);
    CP_COMMIT();

    for (int s = 0; s < nsteps; s++) {
        if (s + 1 < nsteps) {
            stage_load(sb + ((s + 1) & 1) * STG_BYTES, Ah, Al, Bh, Bl,
                       m0, n0, (s + 1) << 5, K, Nmat, tid);
            CP_COMMIT();
            CP_WAIT(1);
        } else {
            CP_WAIT(0);
        }
        __syncthreads();

        const uint32_t base = sb + (s & 1) * STG_BYTES;
        #pragma unroll
        for (int ks = 0; ks < 2; ks++) {
            const uint32_t kx = ks ? 0x20u : 0u;
            uint32_t ah[2][4], al[2][4], bh[8][2], bl[8][2];
            #pragma unroll
            for (int mf = 0; mf < 2; mf++) {
                LDSM4(ah[mf][0], ah[mf][1], ah[mf][2], ah[mf][3], base + (aoff[mf] ^ kx));
                LDSM4(al[mf][0], al[mf][1], al[mf][2], al[mf][3], base + OFF_ALO + (aoff[mf] ^ kx));
            }
            #pragma unroll
            for (int p = 0; p < 4; p++) {
                LDSM4(bh[2*p][0], bh[2*p][1], bh[2*p+1][0], bh[2*p+1][1],
                      base + OFF_BHI + (boff[p] ^ kx));
                LDSM4(bl[2*p][0], bl[2*p][1], bl[2*p+1][0], bl[2*p+1][1],
                      base + OFF_BLO + (boff[p] ^ kx));
            }
            #pragma unroll
            for (int mf = 0; mf < 2; mf++)
                #pragma unroll
                for (int nf = 0; nf < 8; nf++) {
                    MMA16816(acc[mf][nf], ah[mf], bh[nf]);
                    MMA16816(acc[mf][nf], ah[mf], bl[nf]);
                    MMA16816(acc[mf][nf], al[mf], bh[nf]);
                }
        }
        __syncthreads();
    }

    // ---------------- epilogue ----------------
    const int mrow = m0 + wm + (lane >> 2);
    const int ncol = n0 + wn + (lane & 3) * 2;
    #pragma unroll
    for (int mf = 0; mf < 2; mf++) {
        #pragma unroll
        for (int nf = 0; nf < 8; nf++) {
            const int n = ncol + nf * 8;
            #pragma unroll
            for (int half = 0; half < 2; half++) {
                const int m = mrow + mf * 16 + half * 8;
                #pragma unroll
                for (int j = 0; j < 2; j++) {
                    const int nn = n + j;
                    if (nn < Nmat) {
                        float v = acc[mf][nf][half * 2 + j];
                        if (EPI == 1) v = softplusf(v + bias[nn]);
                        if (EPI == 2) v = v + C[(size_t)m * ldc + nn];
                        C[(size_t)m * ldc + nn] = v;
                    }
                }
            }
        }
    }
}

// ======================= misc kernels ========================================
__global__ void copy_kernel(const float* __restrict__ s, float* __restrict__ d, int n) {
    int i = blockIdx.x * blockDim.x + threadIdx.x;
    if (i < n) d[i] = s[i];
}

__global__ void convert_split_kernel(const float* __restrict__ s,
                                     __nv_bfloat16* __restrict__ h,
                                     __nv_bfloat16* __restrict__ l, int n) {
    int i = blockIdx.x * blockDim.x + threadIdx.x;
    if (i < n) { __nv_bfloat16 hv, lv; split_bf16(s[i], hv, lv); h[i] = hv; l[i] = lv; }
}

// extract dbl[:, :64] -> split bf16 [L,64]
__global__ void dbla_kernel(const float* __restrict__ dbl,
                            __nv_bfloat16* __restrict__ h, __nv_bfloat16* __restrict__ l) {
    int i = blockIdx.x * blockDim.x + threadIdx.x;
    if (i >= LSEQ * DTR) return;
    int row = i >> 6, c = i & 63;
    __nv_bfloat16 hv, lv;
    split_bf16(dbl[row * DBLC + c], hv, lv);
    h[i] = hv; l[i] = lv;
}

// layernorm -> split bf16 (BF=1) or fp32 (BF=0)
template<int BF>
__global__ void __launch_bounds__(256) ln_kernel(
    const float* __restrict__ x, const float* __restrict__ w, const float* __restrict__ b,
    float* __restrict__ outf, __nv_bfloat16* __restrict__ oh, __nv_bfloat16* __restrict__ ol)
{
    int row = blockIdx.x, t = threadIdx.x;
    const float* xr = x + row * DM;
    float4 v = *(const float4*)(xr + t * 4);
    float s  = v.x + v.y + v.z + v.w;
    float ss = v.x * v.x + v.y * v.y + v.z * v.z + v.w * v.w;
    #pragma unroll
    for (int o = 16; o; o >>= 1) {
        s  += __shfl_xor_sync(0xffffffffu, s,  o);
        ss += __shfl_xor_sync(0xffffffffu, ss, o);
    }
    __shared__ float sr[8], sq[8], smu, srs;
    int wid = t >> 5, lane = t & 31;
    if (lane == 0) { sr[wid] = s; sq[wid] = ss; }
    __syncthreads();
    if (t == 0) {
        float S = 0.f, SS = 0.f;
        #pragma unroll
        for (int i = 0; i < 8; i++) { S += sr[i]; SS += sq[i]; }
        float mu = S * (1.0f / DM);
        smu = mu; srs = rsqrtf(SS * (1.0f / DM) - mu * mu + 1e-5f);
    }
    __syncthreads();
    float mu = smu, rs = srs;
    float4 wv = *(const float4*)(w + t * 4);
    float4 bv = *(const float4*)(b + t * 4);
    float o0 = (v.x - mu) * rs * wv.x + bv.x;
    float o1 = (v.y - mu) * rs * wv.y + bv.y;
    float o2 = (v.z - mu) * rs * wv.z + bv.z;
    float o3 = (v.w - mu) * rs * wv.w + bv.w;
    size_t base = (size_t)row * DM + t * 4;
    if (BF) {
        __nv_bfloat16 hh, ll;
        split_bf16(o0, hh, ll); oh[base + 0] = hh; ol[base + 0] = ll;
        split_bf16(o1, hh, ll); oh[base + 1] = hh; ol[base + 1] = ll;
        split_bf16(o2, hh, ll); oh[base + 2] = hh; ol[base + 2] = ll;
        split_bf16(o3, hh, ll); oh[base + 3] = hh; ol[base + 3] = ll;
    } else {
        float4 o4; o4.x = o0; o4.y = o1; o4.z = o2; o4.w = o3;
        *(float4*)(outf + base) = o4;
    }
}

// causal depthwise conv(k=4) + silu -> fp32 + split bf16
__global__ void conv_silu_kernel(const float* __restrict__ xz,
                                 const float* __restrict__ cw, const float* __restrict__ cb,
                                 float* __restrict__ xc,
                                 __nv_bfloat16* __restrict__ xch, __nv_bfloat16* __restrict__ xcl)
{
    int idx = blockIdx.x * blockDim.x + threadIdx.x;
    if (idx >= LSEQ * DI) return;
    int l = idx / DI, e = idx - l * DI;
    float acc = cb[e];
    #pragma unroll
    for (int k = 0; k < 4; k++) {
        int ls = l + k - 3;
        if (ls >= 0) acc = fmaf(xz[(size_t)ls * (2 * DI) + e], cw[e * 4 + k], acc);
    }
    float v = siluf(acc);
    xc[idx] = v;
    __nv_bfloat16 hh, ll;
    split_bf16(v, hh, ll);
    xch[idx] = hh; xcl[idx] = ll;
}

// ======= selective scan: smem-staged, cp.async double-buffered ===============
// 16 channels/block (16 threads each: one per state). Chunks of 64 timesteps
// prefetched via cp.async: dt/xc/z rows (16 floats) + B|C rows (32 floats).
#define STT 64
#define NCHUNK (LSEQ / STT)

__global__ void __launch_bounds__(256) scan_kernel(
    const float* __restrict__ dbl, const float* __restrict__ dtf,
    const float* __restrict__ xz, const float* __restrict__ xc,
    const float* __restrict__ A_log, const float* __restrict__ Dp,
    __nv_bfloat16* __restrict__ yh, __nv_bfloat16* __restrict__ yl)
{
    __shared__ float sdt[2][STT][16];
    __shared__ float sxc[2][STT][16];
    __shared__ float sz [2][STT][16];
    __shared__ float sbc[2][STT][32];

    const int t  = threadIdx.x;
    const int n  = t & 15;          // state index
    const int cj = t >> 4;          // channel-in-block 0..15
    const int e0 = blockIdx.x * 16;
    const int e  = e0 + cj;

    const uint32_t a_dt = smem_u32(&sdt[0][0][0]);
    const uint32_t a_xc = smem_u32(&sxc[0][0][0]);
    const uint32_t a_z  = smem_u32(&sz [0][0][0]);
    const uint32_t a_bc = smem_u32(&sbc[0][0][0]);

    const float Aen = -__expf(A_log[e * DS + n]);
    const float Dv  = Dp[e];
    float h = 0.f;

    // per-thread load assignments
    const int lr  = t >> 2;                 // 0..63 row for dt/xc/z
    const int ls  = t & 3;                  // 16B segment (4 floats)
    const int br  = t >> 3;                 // 0..31 row for bc (x2)
    const int bs  = t & 7;                  // 16B segment of 8

    auto load_chunk = [&](int c, int buf) {
        const int l0 = c * STT;
        const uint32_t bo = (uint32_t)buf * (STT * 16 * 4);
        const uint32_t bo2 = (uint32_t)buf * (STT * 32 * 4);
        // dt, xc, z: 64 rows x 64B
        cpa16f(a_dt + bo + (uint32_t)(lr * 64 + ls * 16),
               dtf + (size_t)(l0 + lr) * DI + e0 + ls * 4);
        cpa16f(a_xc + bo + (uint32_t)(lr * 64 + ls * 16),
               xc + (size_t)(l0 + lr) * DI + e0 + ls * 4);
        cpa16f(a_z + bo + (uint32_t)(lr * 64 + ls * 16),
               xz + (size_t)(l0 + lr) * (2 * DI) + DI + e0 + ls * 4);
        // B|C: 64 rows x 128B (two rows per thread)
        #pragma unroll
        for (int it = 0; it < 2; it++) {
            int row = br + it * 32;
            cpa16f(a_bc + bo2 + (uint32_t)(row * 128 + bs * 16),
                   dbl + (size_t)(l0 + row) * DBLC + DTR + bs * 4);
        }
    };

    load_chunk(0, 0);
    CP_COMMIT();

    for (int c = 0; c < NCHUNK; c++) {
        if (c + 1 < NCHUNK) {
            load_chunk(c + 1, (c + 1) & 1);
            CP_COMMIT();
            CP_WAIT(1);
        } else {
            CP_WAIT(0);
        }
        __syncthreads();

        const int buf = c & 1;
        const int lbase = c * STT;
        #pragma unroll 8
        for (int s = 0; s < STT; s++) {
            float dt  = sdt[buf][s][cj];
            float xcv = sxc[buf][s][cj];
            float Bv  = sbc[buf][s][n];
            float Cv  = sbc[buf][s][16 + n];
            float dA  = __expf(dt * Aen);
            h = fmaf(dA, h, dt * xcv * Bv);
            float p = h * Cv;
            p += __shfl_xor_sync(0xffffffffu, p, 8);
            p += __shfl_xor_sync(0xffffffffu, p, 4);
            p += __shfl_xor_sync(0xffffffffu, p, 2);
            p += __shfl_xor_sync(0xffffffffu, p, 1);
            if (n == 0) {
                float zv = sz[buf][s][cj];
                float yv = (p + xcv * Dv) * siluf(zv);
                __nv_bfloat16 hh, ll;
                split_bf16(yv, hh, ll);
                yh[(size_t)(lbase + s) * DI + e] = hh;
                yl[(size_t)(lbase + s) * DI + e] = ll;
            }
        }
        __syncthreads();
    }
}

// ======================= launch ==============================================
extern "C" void kernel_launch(void* const* d_in, const int* in_sizes, int n_in,
                              void* d_out, int out_size)
{
    const float* x_in  = (const float*)d_in[0];
    const float* ln_w  = (const float*)d_in[1];
    const float* ln_b  = (const float*)d_in[2];
    const float* inw   = (const float*)d_in[3];
    const float* cw    = (const float*)d_in[4];
    const float* cb    = (const float*)d_in[5];
    const float* xpw   = (const float*)d_in[6];
    const float* dtw   = (const float*)d_in[7];
    const float* dtb   = (const float*)d_in[8];
    const float* alog  = (const float*)d_in[9];
    const float* dskip = (const float*)d_in[10];
    const float* outw  = (const float*)d_in[11];
    const float* nfw   = (const float*)d_in[12];
    const float* nfb   = (const float*)d_in[13];
    float* out = (float*)d_out;

    float *px, *pxz, *pxc, *pdbl, *pdt;
    __nv_bfloat16 *phh, *phl, *pxch, *pxcl, *pyh, *pyl, *pdah, *pdal;
    __nv_bfloat16 *winh, *winl, *wxph, *wxpl, *wdth, *wdtl, *woth, *wotl;
    cudaGetSymbolAddress((void**)&px,   g_x);
    cudaGetSymbolAddress((void**)&pxz,  g_xz);
    cudaGetSymbolAddress((void**)&pxc,  g_xc);
    cudaGetSymbolAddress((void**)&pdbl, g_dbl);
    cudaGetSymbolAddress((void**)&pdt,  g_dt);
    cudaGetSymbolAddress((void**)&phh,  g_h_h);
    cudaGetSymbolAddress((void**)&phl,  g_h_l);
    cudaGetSymbolAddress((void**)&pxch, g_xc_h);
    cudaGetSymbolAddress((void**)&pxcl, g_xc_l);
    cudaGetSymbolAddress((void**)&pyh,  g_y_h);
    cudaGetSymbolAddress((void**)&pyl,  g_y_l);
    cudaGetSymbolAddress((void**)&pdah, g_da_h);
    cudaGetSymbolAddress((void**)&pdal, g_da_l);
    cudaGetSymbolAddress((void**)&winh, g_inw_h);
    cudaGetSymbolAddress((void**)&winl, g_inw_l);
    cudaGetSymbolAddress((void**)&wxph, g_xpw_h);
    cudaGetSymbolAddress((void**)&wxpl, g_xpw_l);
    cudaGetSymbolAddress((void**)&wdth, g_dtw_h);
    cudaGetSymbolAddress((void**)&wdtl, g_dtw_l);
    cudaGetSymbolAddress((void**)&woth, g_otw_h);
    cudaGetSymbolAddress((void**)&wotl, g_otw_l);

    cudaFuncSetAttribute(gemm_mma<0>, cudaFuncAttributeMaxDynamicSharedMemorySize, 2 * STG_BYTES);
    cudaFuncSetAttribute(gemm_mma<1>, cudaFuncAttributeMaxDynamicSharedMemorySize, 2 * STG_BYTES);
    cudaFuncSetAttribute(gemm_mma<2>, cudaFuncAttributeMaxDynamicSharedMemorySize, 2 * STG_BYTES);

    // residual stream <- input; weight splits
    copy_kernel<<<(LSEQ * DM + 255) / 256, 256>>>(x_in, px, LSEQ * DM);
    { int n = 2 * 2 * DI * DM; convert_split_kernel<<<(n + 255) / 256, 256>>>(inw,  winh, winl, n); }
    { int n = 2 * DBLC * DI;   convert_split_kernel<<<(n + 255) / 256, 256>>>(xpw,  wxph, wxpl, n); }
    { int n = 2 * DI * DTR;    convert_split_kernel<<<(n + 255) / 256, 256>>>(dtw,  wdth, wdtl, n); }
    { int n = 2 * DM * DI;     convert_split_kernel<<<(n + 255) / 256, 256>>>(outw, woth, wotl, n); }

    for (int i = 0; i < 2; i++) {
        // 1) layernorm -> split bf16 h
        ln_kernel<1><<<LSEQ, 256>>>(px, ln_w + i * DM, ln_b + i * DM, nullptr, phh, phl);

        // 2) in_proj: [L,4096] = h @ inw^T  (K=1024)
        gemm_mma<0><<<dim3(2 * DI / 128, LSEQ / 128), 256, 2 * STG_BYTES>>>(
            phh, phl, winh + (size_t)i * 2 * DI * DM, winl + (size_t)i * 2 * DI * DM,
            pxz, 2 * DI, 2 * DI, DM, nullptr);

        // 3) conv + silu
        conv_silu_kernel<<<(LSEQ * DI + 255) / 256, 256>>>(
            pxz, cw + (size_t)i * DI * 4, cb + (size_t)i * DI, pxc, pxch, pxcl);

        // 4) x_proj: [L,96] = xc @ xpw^T (K=2048)
        gemm_mma<0><<<dim3(1, LSEQ / 128), 256, 2 * STG_BYTES>>>(
            pxch, pxcl, wxph + (size_t)i * DBLC * DI, wxpl + (size_t)i * DBLC * DI,
            pdbl, DBLC, DBLC, DI, nullptr);

        // 5) extract dt_lr -> split bf16
        dbla_kernel<<<(LSEQ * DTR + 255) / 256, 256>>>(pdbl, pdah, pdal);

        // 6) dt_proj + softplus: [L,2048] (K=64)
        gemm_mma<1><<<dim3(DI / 128, LSEQ / 128), 256, 2 * STG_BYTES>>>(
            pdah, pdal, wdth + (size_t)i * DI * DTR, wdtl + (size_t)i * DI * DTR,
            pdt, DI, DI, DTR, dtb + (size_t)i * DI);

        // 7) selective scan -> split bf16 y
        scan_kernel<<<DI / 16, 256>>>(
            pdbl, pdt, pxz, pxc,
            alog + (size_t)i * DI * DS, dskip + (size_t)i * DI, pyh, pyl);

        // 8) out_proj + residual (K=2048)
        gemm_mma<2><<<dim3(DM / 128, LSEQ / 128), 256, 2 * STG_BYTES>>>(
            pyh, pyl, woth + (size_t)i * DM * DI, wotl + (size_t)i * DM * DI,
            px, DM, DM, DI, nullptr);
    }

    // final layernorm -> fp32 output
    ln_kernel<0><<<LSEQ, 256>>>(px, nfw, nfb, out, nullptr, nullptr);
}